// round 15
// baseline (speedup 1.0000x reference)
#include <cuda_runtime.h>
#include <cstdint>

// ---------------------------------------------------------------------------
// KWTA: per-sample k-th-largest threshold + masked NHWC->NCHW transpose.
// x: (32, 56, 56, 256) fp32.  dim = 802816, k = ceil(0.2*dim) = 160564.
// out[b][c][h][w] = masked x[b][h][w][c]
// key layout: [31:21]=coarse bin (11b) | [20:10]=fine bin (11b) | [9:0]=low (10b)
// ---------------------------------------------------------------------------

#define B          32
#define HW         3136            // 56*56
#define C          256
#define DIM        802816          // HW*C
#define DIM4       200704          // DIM/4
#define KSEL       160564u
#define NBINS      2048            // top-11-bit histogram
#define CAP        131072          // candidate buffer per sample
#define HBLOCKS    98              // 98*2048 float4 = DIM4 per sample
#define STAGE      2048            // compact smem staging entries

__device__ unsigned g_hist[B * NBINS];    // zeroed at start; re-zeroed by scan_kernel
__device__ unsigned g_hist2[B * NBINS];   // fine hist; re-zeroed by select_kernel
__device__ unsigned g_cnt[B];             // re-zeroed by select_kernel
__device__ unsigned g_bin[B];
__device__ unsigned g_kprime[B];
__device__ unsigned g_cand[B * CAP];
__device__ float    g_thresh[B];

__device__ __forceinline__ unsigned f2key(float f) {
    unsigned u = __float_as_uint(f);
    return (u & 0x80000000u) ? ~u : (u | 0x80000000u);
}

// ---- 1. coarse histogram: two smem replicas (by warp parity) ---------------
__global__ __launch_bounds__(256) void hist_kernel(const float4* __restrict__ x) {
    __shared__ unsigned sh[2 * NBINS];
    int tid = threadIdx.x;
    unsigned rep = ((tid >> 5) & 1) * NBINS;
    #pragma unroll
    for (int i = tid; i < 2 * NBINS; i += 256) sh[i] = 0;
    __syncthreads();

    int s = blockIdx.y;
    const float4* p = x + (size_t)s * DIM4 + (size_t)blockIdx.x * 2048;
    #pragma unroll
    for (int it = 0; it < 8; it++) {
        float4 v = p[tid + it * 256];
        atomicAdd(&sh[rep + (f2key(v.x) >> 21)], 1u);
        atomicAdd(&sh[rep + (f2key(v.y) >> 21)], 1u);
        atomicAdd(&sh[rep + (f2key(v.z) >> 21)], 1u);
        atomicAdd(&sh[rep + (f2key(v.w) >> 21)], 1u);
    }
    __syncthreads();
    for (int i = tid; i < NBINS; i += 256) {
        unsigned c = sh[i] + sh[NBINS + i];
        if (c) atomicAdd(&g_hist[s * NBINS + i], c);
    }
}

// ---- 2. find coarse bin + k'; re-zero g_hist -------------------------------
__global__ void scan_kernel() {
    __shared__ unsigned sh[NBINS];
    int s = blockIdx.x;
    int tid = threadIdx.x;
    for (int i = tid; i < NBINS; i += blockDim.x) sh[i] = g_hist[s * NBINS + i];
    __syncthreads();
    if (tid == 0) {
        unsigned cum = 0;
        int b = NBINS - 1;
        for (; b >= 0; b--) {
            cum += sh[b];
            if (cum >= KSEL) break;
        }
        if (b < 0) b = 0;
        g_bin[s] = (unsigned)b;
        g_kprime[s] = KSEL - (cum - sh[b]);
    }
    for (int i = tid; i < NBINS; i += blockDim.x) g_hist[s * NBINS + i] = 0;
}

// ---- 3. compact: stage matches + build FINE histogram (bits 20:10) ---------
__global__ __launch_bounds__(256) void compact_kernel(const float4* __restrict__ x) {
    __shared__ unsigned stage[STAGE];
    __shared__ unsigned fine[NBINS];
    __shared__ unsigned s_cnt;
    __shared__ unsigned s_base;

    int s = blockIdx.y;
    unsigned bin = g_bin[s];
    int tid = threadIdx.x;
    if (tid == 0) s_cnt = 0;
    #pragma unroll
    for (int i = tid; i < NBINS; i += 256) fine[i] = 0;
    __syncthreads();

    const float4* p = x + (size_t)s * DIM4 + (size_t)blockIdx.x * 2048;

    float4 v[8];
    #pragma unroll
    for (int it = 0; it < 8; it++) v[it] = p[tid + it * 256];

    #pragma unroll
    for (int it = 0; it < 8; it++) {
        unsigned keys[4] = { f2key(v[it].x), f2key(v[it].y),
                             f2key(v[it].z), f2key(v[it].w) };
        #pragma unroll
        for (int q = 0; q < 4; q++) {
            if ((keys[q] >> 21) == bin) {
                atomicAdd(&fine[(keys[q] >> 10) & 0x7FFu], 1u);
                unsigned pos = atomicAdd(&s_cnt, 1u);   // rare (~3.5%)
                if (pos < STAGE) {
                    stage[pos] = keys[q];
                } else {
                    unsigned g = atomicAdd(&g_cnt[s], 1u);
                    if (g < CAP) g_cand[(size_t)s * CAP + g] = keys[q];
                }
            }
        }
    }
    __syncthreads();

    unsigned cnt = s_cnt;
    if (cnt > STAGE) cnt = STAGE;
    if (tid == 0 && cnt) s_base = atomicAdd(&g_cnt[s], cnt);
    __syncthreads();

    if (cnt) {
        unsigned base = s_base;
        for (unsigned i = tid; i < cnt; i += 256) {
            unsigned pos = base + i;
            if (pos < CAP) g_cand[(size_t)s * CAP + pos] = stage[i];
        }
    }
    // sparse merge of fine histogram
    for (int i = tid; i < NBINS; i += 256) {
        unsigned c = fine[i];
        if (c) atomicAdd(&g_hist2[s * NBINS + i], c);
    }
}

// ---- 4. select: fine-bin scan + ONE candidate pass over low 10 bits --------
__global__ __launch_bounds__(512) void select_kernel() {
    __shared__ unsigned fh[NBINS];
    __shared__ unsigned lowh[1024];
    __shared__ unsigned s_fine, s_kpp;
    int s = blockIdx.x;
    int tid = threadIdx.x;
    unsigned n = g_cnt[s];
    if (n > CAP) n = CAP;

    for (int i = tid; i < NBINS; i += 512) {
        fh[i] = g_hist2[s * NBINS + i];
        g_hist2[s * NBINS + i] = 0;           // restore invariant
    }
    for (int i = tid; i < 1024; i += 512) lowh[i] = 0;
    __syncthreads();

    if (tid == 0) {
        unsigned kp = g_kprime[s];
        unsigned cum = 0;
        int f = NBINS - 1;
        for (; f >= 0; f--) {
            cum += fh[f];
            if (cum >= kp) break;
        }
        if (f < 0) f = 0;
        s_fine = (unsigned)f;
        s_kpp = kp - (cum - fh[f]);
    }
    __syncthreads();

    unsigned prefix22 = (g_bin[s] << 11) | s_fine;   // top 22 bits of the key
    for (unsigned i = tid; i < n; i += 512) {
        unsigned key = g_cand[(size_t)s * CAP + i];
        if ((key >> 10) == prefix22)
            atomicAdd(&lowh[key & 0x3FFu], 1u);
    }
    __syncthreads();

    if (tid == 0) {
        unsigned kpp = s_kpp;
        unsigned cum = 0;
        int d = 1023;
        for (; d >= 0; d--) {
            cum += lowh[d];
            if (cum >= kpp) break;
        }
        if (d < 0) d = 0;
        unsigned key = (prefix22 << 10) | (unsigned)d;
        unsigned u = (key & 0x80000000u) ? (key & 0x7FFFFFFFu) : ~key;
        g_thresh[s] = __uint_as_float(u);
        g_cnt[s] = 0;                          // restore invariant
    }
}

// ---- 5. masked transpose: 64x64 tile, float4 both sides, streaming stores --
__global__ __launch_bounds__(256) void mask_transpose_kernel(const float* __restrict__ x,
                                                             float* __restrict__ out) {
    __shared__ float tile[64 * 65];   // tile[c][hw], stride 65
    int b = blockIdx.z;
    float th = g_thresh[b];
    int c0 = blockIdx.x * 64;
    int hw0 = blockIdx.y * 64;
    const float* xin = x + (size_t)b * DIM;
    float* o = out + (size_t)b * DIM;

    int tx = threadIdx.x & 15;
    int ty = threadIdx.x >> 4;
    int c4 = 4 * tx;

    #pragma unroll
    for (int j = 0; j < 4; j++) {
        int row = ty + 16 * j;
        float4 v = *(const float4*)&xin[(size_t)(hw0 + row) * C + (c0 + c4)];
        v.x = (v.x >= th) ? v.x : 0.0f;
        v.y = (v.y >= th) ? v.y : 0.0f;
        v.z = (v.z >= th) ? v.z : 0.0f;
        v.w = (v.w >= th) ? v.w : 0.0f;
        tile[(c4 + 0) * 65 + row] = v.x;
        tile[(c4 + 1) * 65 + row] = v.y;
        tile[(c4 + 2) * 65 + row] = v.z;
        tile[(c4 + 3) * 65 + row] = v.w;
    }
    __syncthreads();

    #pragma unroll
    for (int j = 0; j < 4; j++) {
        int crow = ty + 16 * j;
        float4 w;
        w.x = tile[crow * 65 + 4 * tx + 0];
        w.y = tile[crow * 65 + 4 * tx + 1];
        w.z = tile[crow * 65 + 4 * tx + 2];
        w.w = tile[crow * 65 + 4 * tx + 3];
        __stcs((float4*)&o[(size_t)(c0 + crow) * HW + (hw0 + 4 * tx)], w);
    }
}

// ---------------------------------------------------------------------------
extern "C" void kernel_launch(void* const* d_in, const int* in_sizes, int n_in,
                              void* d_out, int out_size) {
    (void)in_sizes; (void)n_in; (void)out_size;
    const float* x = (const float*)d_in[0];
    float* out = (float*)d_out;

    dim3 hgrid(HBLOCKS, B);
    hist_kernel<<<hgrid, 256>>>((const float4*)x);

    scan_kernel<<<B, 256>>>();

    compact_kernel<<<hgrid, 256>>>((const float4*)x);

    select_kernel<<<B, 512>>>();

    dim3 tgrid(C / 64, HW / 64, B);
    mask_transpose_kernel<<<tgrid, 256>>>(x, out);
}

// round 17
// speedup vs baseline: 1.3122x; 1.3122x over previous
#include <cuda_runtime.h>
#include <cstdint>

// ---------------------------------------------------------------------------
// KWTA: per-sample k-th-largest threshold + masked NHWC->NCHW transpose.
// x: (32, 56, 56, 256) fp32.  dim = 802816, k = ceil(0.2*dim) = 160564.
// out[b][c][h][w] = masked x[b][h][w][c]
// key layout: [31:21]=coarse bin | [20:10]=fine bin | [9:0]=low
// ---------------------------------------------------------------------------

#define B          32
#define HW         3136
#define C          256
#define DIM        802816
#define DIM4       200704
#define KSEL       160564u
#define NBINS      2048
#define CAP        131072
#define HBLOCKS    98
#define STAGE      2048

__device__ unsigned g_hist[B * NBINS];    // zeroed at start; re-zeroed by scan_kernel
__device__ unsigned g_hist2[B * NBINS];   // fine hist; re-zeroed by select_kernel
__device__ unsigned g_cnt[B];             // re-zeroed by select_kernel
__device__ unsigned g_bin[B];
__device__ unsigned g_kprime[B];
__device__ unsigned g_cand[B * CAP];
__device__ float    g_thresh[B];

__device__ __forceinline__ unsigned f2key(float f) {
    unsigned u = __float_as_uint(f);
    return (u & 0x80000000u) ? ~u : (u | 0x80000000u);
}

// Parallel find: largest index b with suffix_sum(h, b) >= kp.
// h: smem histogram of NB bins; ssum: smem scratch of T entries.
// Each thread owns CH = NB/T consecutive bins. Result via out_bin/out_kp (smem).
// Exactly one thread writes (suffix sums strictly decrease across the crossing).
template<int T, int NB>
__device__ __forceinline__ void suffix_find(const unsigned* h, unsigned* ssum,
                                            unsigned kp, int tid,
                                            volatile unsigned* out_bin,
                                            volatile unsigned* out_kp) {
    const int CH = NB / T;
    unsigned csum = 0;
    #pragma unroll
    for (int j = 0; j < CH; j++) csum += h[tid * CH + j];
    ssum[tid] = csum;
    __syncthreads();
    // Hillis-Steele inclusive suffix scan
    #pragma unroll
    for (int off = 1; off < T; off <<= 1) {
        unsigned add = (tid + off < T) ? ssum[tid + off] : 0u;
        __syncthreads();
        ssum[tid] += add;
        __syncthreads();
    }
    unsigned mine  = ssum[tid];
    unsigned after = (tid + 1 < T) ? ssum[tid + 1] : 0u;
    if (mine >= kp && after < kp) {
        unsigned cum = after;
        int bfound = tid * CH;          // fallback (kp>=1 guarantees a hit)
        #pragma unroll
        for (int j = CH - 1; j >= 0; j--) {
            unsigned c = h[tid * CH + j];
            cum += c;
            if (cum >= kp) { bfound = tid * CH + j;
                             *out_kp = kp - (cum - c);
                             *out_bin = (unsigned)bfound;
                             break; }
        }
    }
    __syncthreads();
}

// ---- 1. coarse histogram: two smem replicas (by warp parity) ---------------
__global__ __launch_bounds__(256) void hist_kernel(const float4* __restrict__ x) {
    __shared__ unsigned sh[2 * NBINS];
    int tid = threadIdx.x;
    unsigned rep = ((tid >> 5) & 1) * NBINS;
    #pragma unroll
    for (int i = tid; i < 2 * NBINS; i += 256) sh[i] = 0;
    __syncthreads();

    int s = blockIdx.y;
    const float4* p = x + (size_t)s * DIM4 + (size_t)blockIdx.x * 2048;
    #pragma unroll
    for (int it = 0; it < 8; it++) {
        float4 v = p[tid + it * 256];
        atomicAdd(&sh[rep + (f2key(v.x) >> 21)], 1u);
        atomicAdd(&sh[rep + (f2key(v.y) >> 21)], 1u);
        atomicAdd(&sh[rep + (f2key(v.z) >> 21)], 1u);
        atomicAdd(&sh[rep + (f2key(v.w) >> 21)], 1u);
    }
    __syncthreads();
    for (int i = tid; i < NBINS; i += 256) {
        unsigned c = sh[i] + sh[NBINS + i];
        if (c) atomicAdd(&g_hist[s * NBINS + i], c);
    }
}

// ---- 2. coarse scan (parallel suffix find); re-zero g_hist -----------------
__global__ __launch_bounds__(256) void scan_kernel() {
    __shared__ unsigned sh[NBINS];
    __shared__ unsigned ssum[256];
    __shared__ unsigned r_bin, r_kp;
    int s = blockIdx.x;
    int tid = threadIdx.x;
    for (int i = tid; i < NBINS; i += 256) {
        sh[i] = g_hist[s * NBINS + i];
        g_hist[s * NBINS + i] = 0;
    }
    __syncthreads();
    suffix_find<256, NBINS>(sh, ssum, KSEL, tid, &r_bin, &r_kp);
    if (tid == 0) {
        g_bin[s] = r_bin;
        g_kprime[s] = r_kp;
    }
}

// ---- 3. compact: stage matches + build FINE histogram (bits 20:10) ---------
__global__ __launch_bounds__(256) void compact_kernel(const float4* __restrict__ x) {
    __shared__ unsigned stage[STAGE];
    __shared__ unsigned fine[NBINS];
    __shared__ unsigned s_cnt;
    __shared__ unsigned s_base;

    int s = blockIdx.y;
    unsigned bin = g_bin[s];
    int tid = threadIdx.x;
    if (tid == 0) s_cnt = 0;
    #pragma unroll
    for (int i = tid; i < NBINS; i += 256) fine[i] = 0;
    __syncthreads();

    const float4* p = x + (size_t)s * DIM4 + (size_t)blockIdx.x * 2048;

    float4 v[8];
    #pragma unroll
    for (int it = 0; it < 8; it++) v[it] = p[tid + it * 256];

    #pragma unroll
    for (int it = 0; it < 8; it++) {
        unsigned keys[4] = { f2key(v[it].x), f2key(v[it].y),
                             f2key(v[it].z), f2key(v[it].w) };
        #pragma unroll
        for (int q = 0; q < 4; q++) {
            if ((keys[q] >> 21) == bin) {
                atomicAdd(&fine[(keys[q] >> 10) & 0x7FFu], 1u);
                unsigned pos = atomicAdd(&s_cnt, 1u);   // rare (~3.5%)
                if (pos < STAGE) {
                    stage[pos] = keys[q];
                } else {
                    unsigned g = atomicAdd(&g_cnt[s], 1u);
                    if (g < CAP) g_cand[(size_t)s * CAP + g] = keys[q];
                }
            }
        }
    }
    __syncthreads();

    unsigned cnt = s_cnt;
    if (cnt > STAGE) cnt = STAGE;
    if (tid == 0 && cnt) s_base = atomicAdd(&g_cnt[s], cnt);
    __syncthreads();

    if (cnt) {
        unsigned base = s_base;
        for (unsigned i = tid; i < cnt; i += 256) {
            unsigned pos = base + i;
            if (pos < CAP) g_cand[(size_t)s * CAP + pos] = stage[i];
        }
    }
    for (int i = tid; i < NBINS; i += 256) {
        unsigned c = fine[i];
        if (c) atomicAdd(&g_hist2[s * NBINS + i], c);
    }
}

// ---- 4. select: parallel fine scan + ONE candidate pass + parallel low scan
__global__ __launch_bounds__(512) void select_kernel() {
    __shared__ unsigned fh[NBINS];
    __shared__ unsigned lowh[1024];
    __shared__ unsigned ssum[512];
    __shared__ unsigned r_fine, r_kpp, r_low, r_dummy;
    int s = blockIdx.x;
    int tid = threadIdx.x;
    unsigned n = g_cnt[s];
    if (n > CAP) n = CAP;

    for (int i = tid; i < NBINS; i += 512) {
        fh[i] = g_hist2[s * NBINS + i];
        g_hist2[s * NBINS + i] = 0;
    }
    for (int i = tid; i < 1024; i += 512) lowh[i] = 0;
    __syncthreads();

    suffix_find<512, NBINS>(fh, ssum, g_kprime[s], tid, &r_fine, &r_kpp);

    unsigned prefix22 = (g_bin[s] << 11) | r_fine;
    for (unsigned i = tid; i < n; i += 512) {
        unsigned key = g_cand[(size_t)s * CAP + i];
        if ((key >> 10) == prefix22)
            atomicAdd(&lowh[key & 0x3FFu], 1u);
    }
    __syncthreads();

    suffix_find<512, 1024>(lowh, ssum, r_kpp, tid, &r_low, &r_dummy);

    if (tid == 0) {
        unsigned key = (prefix22 << 10) | r_low;
        unsigned u = (key & 0x80000000u) ? (key & 0x7FFFFFFFu) : ~key;
        g_thresh[s] = __uint_as_float(u);
        g_cnt[s] = 0;
    }
}

// ---- 5. masked transpose: 64x64 tile, float4 both sides, streaming stores --
__global__ __launch_bounds__(256) void mask_transpose_kernel(const float* __restrict__ x,
                                                             float* __restrict__ out) {
    __shared__ float tile[64 * 65];
    int b = blockIdx.z;
    float th = g_thresh[b];
    int c0 = blockIdx.x * 64;
    int hw0 = blockIdx.y * 64;
    const float* xin = x + (size_t)b * DIM;
    float* o = out + (size_t)b * DIM;

    int tx = threadIdx.x & 15;
    int ty = threadIdx.x >> 4;
    int c4 = 4 * tx;

    #pragma unroll
    for (int j = 0; j < 4; j++) {
        int row = ty + 16 * j;
        float4 v = *(const float4*)&xin[(size_t)(hw0 + row) * C + (c0 + c4)];
        v.x = (v.x >= th) ? v.x : 0.0f;
        v.y = (v.y >= th) ? v.y : 0.0f;
        v.z = (v.z >= th) ? v.z : 0.0f;
        v.w = (v.w >= th) ? v.w : 0.0f;
        tile[(c4 + 0) * 65 + row] = v.x;
        tile[(c4 + 1) * 65 + row] = v.y;
        tile[(c4 + 2) * 65 + row] = v.z;
        tile[(c4 + 3) * 65 + row] = v.w;
    }
    __syncthreads();

    #pragma unroll
    for (int j = 0; j < 4; j++) {
        int crow = ty + 16 * j;
        float4 w;
        w.x = tile[crow * 65 + 4 * tx + 0];
        w.y = tile[crow * 65 + 4 * tx + 1];
        w.z = tile[crow * 65 + 4 * tx + 2];
        w.w = tile[crow * 65 + 4 * tx + 3];
        __stcs((float4*)&o[(size_t)(c0 + crow) * HW + (hw0 + 4 * tx)], w);
    }
}

// ---------------------------------------------------------------------------
extern "C" void kernel_launch(void* const* d_in, const int* in_sizes, int n_in,
                              void* d_out, int out_size) {
    (void)in_sizes; (void)n_in; (void)out_size;
    const float* x = (const float*)d_in[0];
    float* out = (float*)d_out;

    dim3 hgrid(HBLOCKS, B);
    hist_kernel<<<hgrid, 256>>>((const float4*)x);

    scan_kernel<<<B, 256>>>();

    compact_kernel<<<hgrid, 256>>>((const float4*)x);

    select_kernel<<<B, 512>>>();

    dim3 tgrid(C / 64, HW / 64, B);
    mask_transpose_kernel<<<tgrid, 256>>>(x, out);
}